// round 15
// baseline (speedup 1.0000x reference)
#include <cuda_runtime.h>
#include <cuda_fp16.h>
#include <math_constants.h>
#include <cstdint>

// Problem shape (fixed): B=4, S=4096, D=1024
#define PB 4
#define PS 4096
#define PD 1024
#define MROWS (PB * PS)   // 16384

// ---------------------------------------------------------------------------
// Global scratch (allocation-guard-safe __device__ arrays)
// ---------------------------------------------------------------------------
__device__ __half g_x16[(size_t)MROWS * PD];
__device__ __half g_Wq16[PD * PD], g_Wk16[PD * PD], g_Wv16[PD * PD];
__device__ __half g_Q16[(size_t)MROWS * PD];
__device__ __half g_K16[(size_t)MROWS * PD];
__device__ __half g_V16[(size_t)MROWS * PD];
__device__ __half g_Pf[(size_t)PB * PS * PS];    // exp scores, fp16
__device__ float g_psum[(size_t)PB * PS * 64];   // per-row partial expsums

// ---------------------------------------------------------------------------
// PTX helpers. cp.async.bulk + mbarrier are sm_90 BASELINE PTX (no arch
// variant suffix) -> expected to assemble under compute_103, unlike tcgen05.
// ---------------------------------------------------------------------------
__device__ __forceinline__ uint32_t smem_u32(const void* p) {
    uint32_t a;
    asm("{ .reg .u64 t; cvta.to.shared.u64 t, %1; cvt.u32.u64 %0, t; }"
        : "=r"(a) : "l"(p));
    return a;
}

__device__ __forceinline__ void cpbulk(uint32_t dst, const void* src,
                                       uint32_t bytes, uint32_t mbar) {
    asm volatile(
        "cp.async.bulk.shared::cluster.global.mbarrier::complete_tx::bytes "
        "[%0], [%1], %2, [%3];"
        :: "r"(dst), "l"(src), "r"(bytes), "r"(mbar) : "memory");
}

__device__ __forceinline__ void mbar_init(uint32_t addr, uint32_t cnt) {
    asm volatile("mbarrier.init.shared.b64 [%0], %1;"
                 :: "r"(addr), "r"(cnt) : "memory");
}
__device__ __forceinline__ void mbar_arrive_tx(uint32_t addr, uint32_t tx) {
    asm volatile("mbarrier.arrive.expect_tx.shared.b64 _, [%0], %1;"
                 :: "r"(addr), "r"(tx) : "memory");
}
__device__ __forceinline__ void mbar_arrive(uint32_t addr) {
    asm volatile("mbarrier.arrive.shared.b64 _, [%0];"
                 :: "r"(addr) : "memory");
}
__device__ __forceinline__ void mbar_wait(uint32_t addr, uint32_t parity) {
    asm volatile(
        "{\n\t"
        ".reg .pred P;\n\t"
        "W_%=: \n\t"
        "mbarrier.try_wait.parity.acquire.cta.shared::cta.b64 P, [%0], %1, 0x989680;\n\t"
        "@P bra.uni D_%=;\n\t"
        "bra.uni W_%=;\n\t"
        "D_%=: \n\t"
        "}"
        :: "r"(addr), "r"(parity) : "memory");
}

__device__ __forceinline__ void ldsm_x4(uint32_t a, uint32_t* r) {
    asm volatile("ldmatrix.sync.aligned.m8n8.x4.shared.b16 {%0,%1,%2,%3}, [%4];"
                 : "=r"(r[0]), "=r"(r[1]), "=r"(r[2]), "=r"(r[3]) : "r"(a));
}
__device__ __forceinline__ void ldsm_x4_t(uint32_t a, uint32_t* r) {
    asm volatile("ldmatrix.sync.aligned.m8n8.x4.trans.shared.b16 {%0,%1,%2,%3}, [%4];"
                 : "=r"(r[0]), "=r"(r[1]), "=r"(r[2]), "=r"(r[3]) : "r"(a));
}

__device__ __forceinline__ void mma_f16(float* c, const uint32_t* a,
                                        const uint32_t* b) {
    asm volatile(
        "mma.sync.aligned.m16n8k16.row.col.f32.f16.f16.f32 "
        "{%0,%1,%2,%3},{%4,%5,%6,%7},{%8,%9},{%0,%1,%2,%3};"
        : "+f"(c[0]), "+f"(c[1]), "+f"(c[2]), "+f"(c[3])
        : "r"(a[0]), "r"(a[1]), "r"(a[2]), "r"(a[3]), "r"(b[0]), "r"(b[1]));
}

__device__ __forceinline__ uint32_t pkh(__half a, __half b) {
    return (uint32_t)__half_as_ushort(a) | ((uint32_t)__half_as_ushort(b) << 16);
}

// ---------------------------------------------------------------------------
// NT GEMM core: CTA 128x128, BK=64, 4 warps (2m x 2n) 64x64, 3 CTAs/SM.
// Tile loads via cp.async.bulk: one 128B row per thread per operand
// (256 bulk ops/chunk vs 2048 LDGSTS) -> LSU relief for the LDSM feed.
// 144B-padded rows preserved (bulk dst stride 144 = 9*16, 16B-aligned).
// EPI=0: +bias, fp16 store (projections). EPI=1: exp, fp16 P + psum (scores).
// ---------------------------------------------------------------------------
#define NT_STAGE 36864
#define NT_SMEM (2 * NT_STAGE + 16)   // 73744: stages + 2 mbarriers

struct ProjSet {
    const __half* W16;
    const float* bias;
    __half* C16;
};
struct ProjArgs { ProjSet s[3]; };

template<int EPI>
__global__ void __launch_bounds__(128, 3)
gemm_nt(const __half* __restrict__ A_, const __half* __restrict__ B_,
        ProjArgs pa, __half* __restrict__ Pf, float* __restrict__ psum)
{
    extern __shared__ char smem[];
    const uint32_t sb0  = smem_u32(smem);
    const uint32_t mbar = sb0 + 2 * NT_STAGE;
    const int tid  = threadIdx.x;
    const int lane = tid & 31;
    const int wid  = tid >> 5;
    const int warp_m = wid & 1;
    const int warp_n = wid >> 1;
    const int bz = blockIdx.z;

    const __half* A;
    const __half* B;
    const float* bias = nullptr;
    __half* C = nullptr;
    if (EPI == 0) {
        A = A_;
        const ProjSet& s = pa.s[bz];
        B = s.W16; bias = s.bias; C = s.C16;
    } else {
        A = A_ + (size_t)bz * PS * PD;
        B = B_ + (size_t)bz * PS * PD;
        C = Pf + (size_t)bz * PS * PS;
    }

    const int row0 = blockIdx.y * 128;
    const int col0 = blockIdx.x * 128;
    const int ldc  = (EPI == 0) ? PD : PS;

    float acc[4][8][4];
#pragma unroll
    for (int i = 0; i < 4; i++)
#pragma unroll
        for (int n = 0; n < 8; n++)
#pragma unroll
            for (int j = 0; j < 4; j++) acc[i][n][j] = 0.0f;

    const int nk = PD >> 6;   // 16 chunks of BK=64

    if (tid == 0) { mbar_init(mbar, 128); mbar_init(mbar + 8, 128); }
    __syncthreads();

    // every thread: expect 256B, copy one A row (128B) + one B row (128B)
    auto load_stage = [&](int s, int ki) {
        const uint32_t sb = sb0 + s * NT_STAGE;
        const uint32_t mb = mbar + s * 8;
        const int k0 = ki << 6;
        mbar_arrive_tx(mb, 256);
        cpbulk(sb + tid * 144,
               A + (size_t)(row0 + tid) * PD + k0, 128, mb);
        cpbulk(sb + 18432 + tid * 144,
               B + (size_t)(col0 + tid) * PD + k0, 128, mb);
    };

    int ph0 = 0, ph1 = 0;
    load_stage(0, 0);
    mbar_wait(mbar, ph0); ph0 ^= 1;
    __syncthreads();

    for (int i = 0; i < nk; i++) {
        if (i + 1 < nk) load_stage((i + 1) & 1, i + 1);

        const uint32_t sA0 = sb0 + (i & 1) * NT_STAGE;
        const uint32_t sB0 = sA0 + 18432;

#pragma unroll
        for (int kk = 0; kk < 4; kk++) {
            const int k16 = kk << 4;

            uint32_t a[4][4];
#pragma unroll
            for (int mi = 0; mi < 4; mi++) {
                int m = warp_m * 64 + mi * 16 + (lane & 15);
                int k = k16 + ((lane & 16) ? 8 : 0);
                ldsm_x4(sA0 + m * 144 + k * 2, a[mi]);
            }

#pragma unroll
            for (int nt = 0; nt < 4; nt++) {
                uint32_t b4[4];
                int n = warp_n * 64 + nt * 16 + ((lane & 16) ? 8 : 0) + (lane & 7);
                int k = k16 + (lane & 8);
                ldsm_x4(sB0 + n * 144 + k * 2, b4);
#pragma unroll
                for (int mi = 0; mi < 4; mi++)
#pragma unroll
                    for (int nn = 0; nn < 2; nn++)
                        mma_f16(acc[mi][2 * nt + nn], a[mi], b4 + 2 * nn);
            }
        }

        if (i + 1 < nk) {
            const int s = (i + 1) & 1;
            mbar_wait(mbar + s * 8, s ? ph1 : ph0);
            if (s) ph1 ^= 1; else ph0 ^= 1;
            __syncthreads();
        }
    }

    // ---------------- epilogue ----------------
    if (EPI == 0) {
#pragma unroll
        for (int mi = 0; mi < 4; mi++) {
            const int rbase = row0 + warp_m * 64 + mi * 16 + (lane >> 2);
#pragma unroll
            for (int n = 0; n < 8; n++) {
                const int cb = col0 + warp_n * 64 + n * 8 + 2 * (lane & 3);
                float b0 = bias[cb], b1 = bias[cb + 1];
                __half h0 = __float2half(acc[mi][n][0] + b0);
                __half h1 = __float2half(acc[mi][n][1] + b1);
                __half h2 = __float2half(acc[mi][n][2] + b0);
                __half h3 = __float2half(acc[mi][n][3] + b1);
                *reinterpret_cast<uint32_t*>(C + (size_t)rbase * ldc + cb) = pkh(h0, h1);
                *reinterpret_cast<uint32_t*>(C + (size_t)(rbase + 8) * ldc + cb) = pkh(h2, h3);
            }
        }
    } else {
        float rs[4][2] = {{0,0},{0,0},{0,0},{0,0}};
        const float scale = 0.03125f;
#pragma unroll
        for (int mi = 0; mi < 4; mi++) {
            const int rbase = row0 + warp_m * 64 + mi * 16 + (lane >> 2);
#pragma unroll
            for (int n = 0; n < 8; n++) {
                const int cb = col0 + warp_n * 64 + n * 8 + 2 * (lane & 3);
                float e0 = __expf(acc[mi][n][0] * scale);
                float e1 = __expf(acc[mi][n][1] * scale);
                float e2 = __expf(acc[mi][n][2] * scale);
                float e3 = __expf(acc[mi][n][3] * scale);
                __half q0 = __float2half(e0), q1 = __float2half(e1);
                __half q2 = __float2half(e2), q3 = __float2half(e3);
                rs[mi][0] += __half2float(q0) + __half2float(q1);
                rs[mi][1] += __half2float(q2) + __half2float(q3);
                *reinterpret_cast<uint32_t*>(C + (size_t)rbase * ldc + cb) = pkh(q0, q1);
                *reinterpret_cast<uint32_t*>(C + (size_t)(rbase + 8) * ldc + cb) = pkh(q2, q3);
            }
        }
#pragma unroll
        for (int mi = 0; mi < 4; mi++)
#pragma unroll
            for (int h = 0; h < 2; h++) {
                rs[mi][h] += __shfl_xor_sync(0xffffffffu, rs[mi][h], 1);
                rs[mi][h] += __shfl_xor_sync(0xffffffffu, rs[mi][h], 2);
            }
        if ((lane & 3) == 0) {
            const int q = lane >> 2;
            const int t = blockIdx.x * 2 + warp_n;
#pragma unroll
            for (int mi = 0; mi < 4; mi++) {
                const int rl = row0 + warp_m * 64 + mi * 16 + q;
                const size_t rb = (size_t)bz * PS;
                psum[(rb + rl) * 64 + t]     = rs[mi][0];
                psum[(rb + rl + 8) * 64 + t] = rs[mi][1];
            }
        }
    }
}

// ---------------------------------------------------------------------------
// PV GEMM (NN): out[64x128] = (P @ V) * (1/rowsum). CTA 64x128, 4 CTAs/SM.
// Bulk loads: threads 0-63 copy one P row (128B) + one V row (256B).
// Rowsum folded into prologue.
// ---------------------------------------------------------------------------
#define PV_STAGE 26624
#define PV_SMEM (2 * PV_STAGE + 16 + 256)   // stages + mbars + inv

__global__ void __launch_bounds__(128, 4)
gemm_pv(const __half* __restrict__ Pf, const __half* __restrict__ V16,
        float* __restrict__ out, const float* __restrict__ psum)
{
    extern __shared__ char smem[];
    const uint32_t sb0  = smem_u32(smem);
    const uint32_t mbar = sb0 + 2 * PV_STAGE;
    float* inv_s = reinterpret_cast<float*>(smem + 2 * PV_STAGE + 16);
    const int tid  = threadIdx.x;
    const int lane = tid & 31;
    const int wid  = tid >> 5;
    const int warp_m = wid & 1;     // 2 warps x 32 rows
    const int warp_n = wid >> 1;    // 2 warps x 64 cols
    const int bz = blockIdx.z;
    const int row0 = blockIdx.y * 64;
    const int col0 = blockIdx.x * 128;

    const __half* A = Pf  + (size_t)bz * PS * PS;
    const __half* B = V16 + (size_t)bz * PS * PD;

    float acc[2][8][4];
#pragma unroll
    for (int i = 0; i < 2; i++)
#pragma unroll
        for (int n = 0; n < 8; n++)
#pragma unroll
            for (int j = 0; j < 4; j++) acc[i][n][j] = 0.0f;

    const int nk = PS >> 6;   // 64 chunks of BK=64

    if (tid == 0) { mbar_init(mbar, 128); mbar_init(mbar + 8, 128); }
    __syncthreads();

    // threads 0-63: expect 384B, copy A row (128B) + V row (256B); rest arrive
    auto load_stage = [&](int s, int ki) {
        const uint32_t sb = sb0 + s * PV_STAGE;
        const uint32_t mb = mbar + s * 8;
        const int k0 = ki << 6;
        if (tid < 64) {
            mbar_arrive_tx(mb, 384);
            cpbulk(sb + tid * 144,
                   A + (size_t)(row0 + tid) * PS + k0, 128, mb);
            cpbulk(sb + 9216 + tid * 272,
                   B + (size_t)(k0 + tid) * PD + col0, 256, mb);
        } else {
            mbar_arrive(mb);
        }
    };

    int ph0 = 0, ph1 = 0;
    load_stage(0, 0);

    // rowsum -> 1/sum for this CTA's 64 rows (overlapped with stage-0 bulk)
    if (tid < 64) {
        const float* pr = psum + ((size_t)bz * PS + row0 + tid) * 64;
        float s = 0.0f;
#pragma unroll
        for (int j = 0; j < 16; j++) {
            float4 v = reinterpret_cast<const float4*>(pr)[j];
            s += (v.x + v.y) + (v.z + v.w);
        }
        inv_s[tid] = 1.0f / s;
    }

    mbar_wait(mbar, ph0); ph0 ^= 1;
    __syncthreads();   // covers stage 0 + inv_s visibility

    for (int i = 0; i < nk; i++) {
        if (i + 1 < nk) load_stage((i + 1) & 1, i + 1);

        const uint32_t sA0 = sb0 + (i & 1) * PV_STAGE;
        const uint32_t sB0 = sA0 + 9216;

#pragma unroll
        for (int kk = 0; kk < 4; kk++) {
            const int k16 = kk << 4;

            uint32_t a[2][4];
#pragma unroll
            for (int mi = 0; mi < 2; mi++) {
                int m = warp_m * 32 + mi * 16 + (lane & 15);
                int k = k16 + ((lane & 16) ? 8 : 0);
                ldsm_x4(sA0 + m * 144 + k * 2, a[mi]);
            }

#pragma unroll
            for (int nt = 0; nt < 4; nt++) {
                uint32_t b4[4];
                int k = k16 + (lane & 15);
                int n = warp_n * 64 + nt * 16 + ((lane & 16) ? 8 : 0);
                ldsm_x4_t(sB0 + k * 272 + n * 2, b4);
#pragma unroll
                for (int mi = 0; mi < 2; mi++)
#pragma unroll
                    for (int nn = 0; nn < 2; nn++)
                        mma_f16(acc[mi][2 * nt + nn], a[mi], b4 + 2 * nn);
            }
        }

        if (i + 1 < nk) {
            const int s = (i + 1) & 1;
            mbar_wait(mbar + s * 8, s ? ph1 : ph0);
            if (s) ph1 ^= 1; else ph0 ^= 1;
            __syncthreads();
        }
    }

    // epilogue: scale by 1/rowsum
#pragma unroll
    for (int mi = 0; mi < 2; mi++) {
        const int rloc = warp_m * 32 + mi * 16 + (lane >> 2);
        const int rbase = row0 + rloc;
        const float iv0 = inv_s[rloc];
        const float iv1 = inv_s[rloc + 8];
        float* base = out + (size_t)bz * PS * PD;
#pragma unroll
        for (int n = 0; n < 8; n++) {
            const int cb = col0 + warp_n * 64 + n * 8 + 2 * (lane & 3);
            float2 v0 = make_float2(acc[mi][n][0] * iv0, acc[mi][n][1] * iv0);
            float2 v1 = make_float2(acc[mi][n][2] * iv1, acc[mi][n][3] * iv1);
            *reinterpret_cast<float2*>(base + (size_t)rbase * PD + cb) = v0;
            *reinterpret_cast<float2*>(base + (size_t)(rbase + 8) * PD + cb) = v1;
        }
    }
}

// ---------------------------------------------------------------------------
// Merged splits: x, Wq, Wk, Wv -> plain fp16 (one launch)
// ---------------------------------------------------------------------------
struct SplitArgs {
    const float* src[4];
    __half* dst[4];
};

__global__ void __launch_bounds__(256)
split_all(SplitArgs sa)
{
    int bid = blockIdx.x;
    int which, boff;
    if (bid < 16384) { which = 0; boff = bid; }
    else { which = 1 + ((bid - 16384) >> 10); boff = (bid - 16384) & 1023; }

    size_t i = (size_t)boff * 256 + threadIdx.x;
    float4 v = reinterpret_cast<const float4*>(sa.src[which])[i];
    __half h0 = __float2half(v.x), h1 = __float2half(v.y);
    __half h2 = __float2half(v.z), h3 = __float2half(v.w);
    reinterpret_cast<uint2*>(sa.dst[which])[i] = make_uint2(pkh(h0, h1), pkh(h2, h3));
}

// ---------------------------------------------------------------------------
// Launcher
// ---------------------------------------------------------------------------
extern "C" void kernel_launch(void* const* d_in, const int* in_sizes, int n_in,
                              void* d_out, int out_size)
{
    (void)in_sizes; (void)n_in; (void)out_size;
    const float* x  = (const float*)d_in[0];
    const float* Wq = (const float*)d_in[1];
    const float* bq = (const float*)d_in[2];
    const float* Wk = (const float*)d_in[3];
    const float* bk = (const float*)d_in[4];
    const float* Wv = (const float*)d_in[5];
    const float* bv = (const float*)d_in[6];
    float* out = (float*)d_out;

    __half *x16, *Wq16, *Wk16, *Wv16, *Q16, *K16, *V16, *Pf;
    float *psum;
    cudaGetSymbolAddress((void**)&x16,  g_x16);
    cudaGetSymbolAddress((void**)&Wq16, g_Wq16);
    cudaGetSymbolAddress((void**)&Wk16, g_Wk16);
    cudaGetSymbolAddress((void**)&Wv16, g_Wv16);
    cudaGetSymbolAddress((void**)&Q16,  g_Q16);
    cudaGetSymbolAddress((void**)&K16,  g_K16);
    cudaGetSymbolAddress((void**)&V16,  g_V16);
    cudaGetSymbolAddress((void**)&Pf,   g_Pf);
    cudaGetSymbolAddress((void**)&psum, g_psum);

    cudaFuncSetAttribute((const void*)gemm_nt<0>,
                         cudaFuncAttributeMaxDynamicSharedMemorySize, NT_SMEM);
    cudaFuncSetAttribute((const void*)gemm_nt<1>,
                         cudaFuncAttributeMaxDynamicSharedMemorySize, NT_SMEM);
    cudaFuncSetAttribute((const void*)gemm_pv,
                         cudaFuncAttributeMaxDynamicSharedMemorySize, PV_SMEM);

    // 1) merged splits: x + Wq/Wk/Wv -> plain fp16
    SplitArgs sa;
    sa.src[0] = x;  sa.dst[0] = x16;
    sa.src[1] = Wq; sa.dst[1] = Wq16;
    sa.src[2] = Wk; sa.dst[2] = Wk16;
    sa.src[3] = Wv; sa.dst[3] = Wv16;
    split_all<<<16384 + 3 * 1024, 256>>>(sa);

    // 2) merged projections: z=0/1/2 -> Q/K/V plain fp16
    ProjArgs pa;
    pa.s[0] = { Wq16, bq, Q16 };
    pa.s[1] = { Wk16, bk, K16 };
    pa.s[2] = { Wv16, bv, V16 };
    ProjArgs dummy = {};
    dim3 gp(PD / 128, MROWS / 128, 3);
    gemm_nt<0><<<gp, 128, NT_SMEM>>>(x16, nullptr, pa, nullptr, nullptr);

    // 3) scores + fused exp -> fp16 P, psum partials
    dim3 gs(PS / 128, PS / 128, PB);
    gemm_nt<1><<<gs, 128, NT_SMEM>>>(Q16, K16, dummy, Pf, psum);

    // 4) out = (P @ V) * inv   (rowsum folded into PV prologue)
    dim3 go(PD / 128, PS / 64, PB);
    gemm_pv<<<go, 128, PV_SMEM>>>(Pf, V16, out, psum);
}

// round 16
// speedup vs baseline: 1.4350x; 1.4350x over previous
#include <cuda_runtime.h>
#include <cuda_fp16.h>
#include <math_constants.h>
#include <cstdint>

// Problem shape (fixed): B=4, S=4096, D=1024
#define PB 4
#define PS 4096
#define PD 1024
#define MROWS (PB * PS)   // 16384

// ---------------------------------------------------------------------------
// Global scratch (allocation-guard-safe __device__ arrays)
// ---------------------------------------------------------------------------
__device__ __half g_x16[(size_t)MROWS * PD];
__device__ __half g_Wq16[PD * PD], g_Wk16[PD * PD], g_Wv16[PD * PD];
__device__ __half g_Q16[(size_t)MROWS * PD];
__device__ __half g_K16[(size_t)MROWS * PD];
__device__ __half g_V16[(size_t)MROWS * PD];
__device__ __half g_Pf[(size_t)PB * PS * PS];    // exp scores, fp16
__device__ float g_psum[(size_t)PB * PS * 64];   // per-row partial expsums

// ---------------------------------------------------------------------------
// PTX helpers (baseline sm_80+ features only: compile-safe under compute_103)
// ---------------------------------------------------------------------------
__device__ __forceinline__ uint32_t smem_u32(const void* p) {
    uint32_t a;
    asm("{ .reg .u64 t; cvta.to.shared.u64 t, %1; cvt.u32.u64 %0, t; }"
        : "=r"(a) : "l"(p));
    return a;
}

__device__ __forceinline__ void cp16(uint32_t s, const void* g) {
    asm volatile("cp.async.cg.shared.global [%0], [%1], 16;" :: "r"(s), "l"(g));
}
__device__ __forceinline__ void cp_commit() {
    asm volatile("cp.async.commit_group;" ::: "memory");
}
template<int N>
__device__ __forceinline__ void cp_wait() {
    asm volatile("cp.async.wait_group %0;" :: "n"(N) : "memory");
}

__device__ __forceinline__ void ldsm_x4(uint32_t a, uint32_t* r) {
    asm volatile("ldmatrix.sync.aligned.m8n8.x4.shared.b16 {%0,%1,%2,%3}, [%4];"
                 : "=r"(r[0]), "=r"(r[1]), "=r"(r[2]), "=r"(r[3]) : "r"(a));
}
__device__ __forceinline__ void ldsm_x4_t(uint32_t a, uint32_t* r) {
    asm volatile("ldmatrix.sync.aligned.m8n8.x4.trans.shared.b16 {%0,%1,%2,%3}, [%4];"
                 : "=r"(r[0]), "=r"(r[1]), "=r"(r[2]), "=r"(r[3]) : "r"(a));
}

__device__ __forceinline__ void mma_f16(float* c, const uint32_t* a,
                                        const uint32_t* b) {
    asm volatile(
        "mma.sync.aligned.m16n8k16.row.col.f32.f16.f16.f32 "
        "{%0,%1,%2,%3},{%4,%5,%6,%7},{%8,%9},{%0,%1,%2,%3};"
        : "+f"(c[0]), "+f"(c[1]), "+f"(c[2]), "+f"(c[3])
        : "r"(a[0]), "r"(a[1]), "r"(a[2]), "r"(a[3]), "r"(b[0]), "r"(b[1]));
}

__device__ __forceinline__ uint32_t pkh(__half a, __half b) {
    return (uint32_t)__half_as_ushort(a) | ((uint32_t)__half_as_ushort(b) << 16);
}
// one-instruction pack: d = {lo, hi} as fp16x2
__device__ __forceinline__ uint32_t pk2h(float lo, float hi) {
    uint32_t d;
    asm("cvt.rn.f16x2.f32 %0, %1, %2;" : "=r"(d) : "f"(hi), "f"(lo));
    return d;
}

// ---------------------------------------------------------------------------
// NT GEMM core (fp16 1-term): CTA 128x128, BK=64, 4 warps (2m x 2n) 64x64.
// 144B-padded rows, conflict-free. Stage 36864 x2; occupancy 3 CTAs/SM.
// EPI=0: +bias, fp16 store (projections). EPI=1: exp, fp16 P + psum (scores).
// ---------------------------------------------------------------------------
#define NT_STAGE 36864
#define NT_SMEM (2 * NT_STAGE)   // 73728

struct ProjSet {
    const __half* W16;
    const float* bias;
    __half* C16;
};
struct ProjArgs { ProjSet s[3]; };

template<int EPI>
__global__ void __launch_bounds__(128, 3)
gemm_nt(const __half* __restrict__ A_, const __half* __restrict__ B_,
        ProjArgs pa, __half* __restrict__ Pf, float* __restrict__ psum)
{
    extern __shared__ char smem[];
    const uint32_t sb0 = smem_u32(smem);
    const int tid  = threadIdx.x;
    const int lane = tid & 31;
    const int wid  = tid >> 5;
    const int warp_m = wid & 1;
    const int warp_n = wid >> 1;
    const int bz = blockIdx.z;

    const __half* A;
    const __half* B;
    const float* bias = nullptr;
    __half* C = nullptr;
    if (EPI == 0) {
        A = A_;
        const ProjSet& s = pa.s[bz];
        B = s.W16; bias = s.bias; C = s.C16;
    } else {
        A = A_ + (size_t)bz * PS * PD;
        B = B_ + (size_t)bz * PS * PD;
        C = Pf + (size_t)bz * PS * PS;
    }

    const int row0 = blockIdx.y * 128;
    const int col0 = blockIdx.x * 128;
    const int ldc  = (EPI == 0) ? PD : PS;

    float acc[4][8][4];
#pragma unroll
    for (int i = 0; i < 4; i++)
#pragma unroll
        for (int n = 0; n < 8; n++)
#pragma unroll
            for (int j = 0; j < 4; j++) acc[i][n][j] = 0.0f;

    const int nk = PD >> 6;   // 16 chunks of BK=64

    auto load_stage = [&](int stage, int ki) {
        const uint32_t sb = sb0 + stage * NT_STAGE;
        const int k0 = ki << 6;
#pragma unroll
        for (int it = 0; it < 8; it++) {
            int idx = tid + (it << 7);
            int r = idx >> 3, c8 = idx & 7;
            cp16(sb + r * 144 + c8 * 16,
                 A + (size_t)(row0 + r) * PD + k0 + c8 * 8);
        }
#pragma unroll
        for (int it = 0; it < 8; it++) {
            int idx = tid + (it << 7);
            int r = idx >> 3, c8 = idx & 7;
            cp16(sb + 18432 + r * 144 + c8 * 16,
                 B + (size_t)(col0 + r) * PD + k0 + c8 * 8);
        }
        cp_commit();
    };

    load_stage(0, 0);
    cp_wait<0>();
    __syncthreads();

    for (int i = 0; i < nk; i++) {
        if (i + 1 < nk) load_stage((i + 1) & 1, i + 1);

        const uint32_t sA0 = sb0 + (i & 1) * NT_STAGE;
        const uint32_t sB0 = sA0 + 18432;

#pragma unroll
        for (int kk = 0; kk < 4; kk++) {
            const int k16 = kk << 4;

            uint32_t a[4][4];
#pragma unroll
            for (int mi = 0; mi < 4; mi++) {
                int m = warp_m * 64 + mi * 16 + (lane & 15);
                int k = k16 + ((lane & 16) ? 8 : 0);
                ldsm_x4(sA0 + m * 144 + k * 2, a[mi]);
            }

#pragma unroll
            for (int nt = 0; nt < 4; nt++) {
                uint32_t b4[4];
                int n = warp_n * 64 + nt * 16 + ((lane & 16) ? 8 : 0) + (lane & 7);
                int k = k16 + (lane & 8);
                ldsm_x4(sB0 + n * 144 + k * 2, b4);
#pragma unroll
                for (int mi = 0; mi < 4; mi++)
#pragma unroll
                    for (int nn = 0; nn < 2; nn++)
                        mma_f16(acc[mi][2 * nt + nn], a[mi], b4 + 2 * nn);
            }
        }

        if (i + 1 < nk) {
            cp_wait<0>();
            __syncthreads();
        }
    }

    // ---------------- epilogue ----------------
    if (EPI == 0) {
#pragma unroll
        for (int mi = 0; mi < 4; mi++) {
            const int rbase = row0 + warp_m * 64 + mi * 16 + (lane >> 2);
#pragma unroll
            for (int n = 0; n < 8; n++) {
                const int cb = col0 + warp_n * 64 + n * 8 + 2 * (lane & 3);
                float b0 = bias[cb], b1 = bias[cb + 1];
                uint32_t p01 = pk2h(acc[mi][n][0] + b0, acc[mi][n][1] + b1);
                uint32_t p23 = pk2h(acc[mi][n][2] + b0, acc[mi][n][3] + b1);
                *reinterpret_cast<uint32_t*>(C + (size_t)rbase * ldc + cb) = p01;
                *reinterpret_cast<uint32_t*>(C + (size_t)(rbase + 8) * ldc + cb) = p23;
            }
        }
    } else {
        float rs[4][2] = {{0,0},{0,0},{0,0},{0,0}};
        const float scale = 0.03125f;
#pragma unroll
        for (int mi = 0; mi < 4; mi++) {
            const int rbase = row0 + warp_m * 64 + mi * 16 + (lane >> 2);
#pragma unroll
            for (int n = 0; n < 8; n++) {
                const int cb = col0 + warp_n * 64 + n * 8 + 2 * (lane & 3);
                float e0 = __expf(acc[mi][n][0] * scale);
                float e1 = __expf(acc[mi][n][1] * scale);
                float e2 = __expf(acc[mi][n][2] * scale);
                float e3 = __expf(acc[mi][n][3] * scale);
                // rowsums from fp32 values (uniform ~2e-6 deviation from the
                // rounded sum; cancels in normalization)
                rs[mi][0] += e0 + e1;
                rs[mi][1] += e2 + e3;
                *reinterpret_cast<uint32_t*>(C + (size_t)rbase * ldc + cb)
                    = pk2h(e0, e1);
                *reinterpret_cast<uint32_t*>(C + (size_t)(rbase + 8) * ldc + cb)
                    = pk2h(e2, e3);
            }
        }
#pragma unroll
        for (int mi = 0; mi < 4; mi++)
#pragma unroll
            for (int h = 0; h < 2; h++) {
                rs[mi][h] += __shfl_xor_sync(0xffffffffu, rs[mi][h], 1);
                rs[mi][h] += __shfl_xor_sync(0xffffffffu, rs[mi][h], 2);
            }
        if ((lane & 3) == 0) {
            const int q = lane >> 2;
            const int t = blockIdx.x * 2 + warp_n;
#pragma unroll
            for (int mi = 0; mi < 4; mi++) {
                const int rl = row0 + warp_m * 64 + mi * 16 + q;
                const size_t rb = (size_t)bz * PS;
                psum[(rb + rl) * 64 + t]     = rs[mi][0];
                psum[(rb + rl + 8) * 64 + t] = rs[mi][1];
            }
        }
    }
}

// ---------------------------------------------------------------------------
// PV GEMM (fp16 1-term, NN): out[64x128] = (P @ V) * (1/rowsum).
// CTA 64x128, BK=64, 4 warps (2m x 2n) 32x64, 4 CTAs/SM.
// Rowsum folded into prologue (threads 0-63, one row each).
// ---------------------------------------------------------------------------
#define PV_STAGE 26624
#define PV_SMEM (2 * PV_STAGE + 256)   // 53504

__global__ void __launch_bounds__(128, 4)
gemm_pv(const __half* __restrict__ Pf, const __half* __restrict__ V16,
        float* __restrict__ out, const float* __restrict__ psum)
{
    extern __shared__ char smem[];
    const uint32_t sb0 = smem_u32(smem);
    float* inv_s = reinterpret_cast<float*>(smem + 2 * PV_STAGE);
    const int tid  = threadIdx.x;
    const int lane = tid & 31;
    const int wid  = tid >> 5;
    const int warp_m = wid & 1;     // 2 warps x 32 rows
    const int warp_n = wid >> 1;    // 2 warps x 64 cols
    const int bz = blockIdx.z;
    const int row0 = blockIdx.y * 64;
    const int col0 = blockIdx.x * 128;

    const __half* A = Pf  + (size_t)bz * PS * PS;
    const __half* B = V16 + (size_t)bz * PS * PD;

    float acc[2][8][4];
#pragma unroll
    for (int i = 0; i < 2; i++)
#pragma unroll
        for (int n = 0; n < 8; n++)
#pragma unroll
            for (int j = 0; j < 4; j++) acc[i][n][j] = 0.0f;

    const int nk = PS >> 6;   // 64 chunks of BK=64

    auto load_stage = [&](int stage, int ki) {
        const uint32_t sb = sb0 + stage * PV_STAGE;
        const int k0 = ki << 6;
        // A: 64 rows x 128B = 512 x 16B chunks, 4/thread, 144B rows
#pragma unroll
        for (int it = 0; it < 4; it++) {
            int idx = tid + (it << 7);
            int r = idx >> 3, c8 = idx & 7;
            cp16(sb + r * 144 + c8 * 16,
                 A + (size_t)(row0 + r) * PS + k0 + c8 * 8);
        }
        // B: 64 k-rows x 256B = 1024 x 16B chunks, 8/thread, 272B rows
#pragma unroll
        for (int it = 0; it < 8; it++) {
            int idx = tid + (it << 7);
            int r = idx >> 4, c16 = idx & 15;
            cp16(sb + 9216 + r * 272 + c16 * 16,
                 B + (size_t)(k0 + r) * PD + col0 + c16 * 8);
        }
        cp_commit();
    };

    load_stage(0, 0);

    // rowsum -> 1/sum for this CTA's 64 rows (overlapped with prologue load)
    if (tid < 64) {
        const float* pr = psum + ((size_t)bz * PS + row0 + tid) * 64;
        float s = 0.0f;
#pragma unroll
        for (int j = 0; j < 16; j++) {
            float4 v = reinterpret_cast<const float4*>(pr)[j];
            s += (v.x + v.y) + (v.z + v.w);
        }
        inv_s[tid] = 1.0f / s;
    }

    cp_wait<0>();
    __syncthreads();   // covers both stage 0 and inv_s visibility

    for (int i = 0; i < nk; i++) {
        if (i + 1 < nk) load_stage((i + 1) & 1, i + 1);

        const uint32_t sA0 = sb0 + (i & 1) * PV_STAGE;
        const uint32_t sB0 = sA0 + 9216;

#pragma unroll
        for (int kk = 0; kk < 4; kk++) {
            const int k16 = kk << 4;

            uint32_t a[2][4];
#pragma unroll
            for (int mi = 0; mi < 2; mi++) {
                int m = warp_m * 32 + mi * 16 + (lane & 15);
                int k = k16 + ((lane & 16) ? 8 : 0);
                ldsm_x4(sA0 + m * 144 + k * 2, a[mi]);
            }

#pragma unroll
            for (int nt = 0; nt < 4; nt++) {
                uint32_t b4[4];
                int k = k16 + (lane & 15);
                int n = warp_n * 64 + nt * 16 + ((lane & 16) ? 8 : 0);
                ldsm_x4_t(sB0 + k * 272 + n * 2, b4);
#pragma unroll
                for (int mi = 0; mi < 2; mi++)
#pragma unroll
                    for (int nn = 0; nn < 2; nn++)
                        mma_f16(acc[mi][2 * nt + nn], a[mi], b4 + 2 * nn);
            }
        }

        if (i + 1 < nk) {
            cp_wait<0>();
            __syncthreads();
        }
    }

    // epilogue: scale by 1/rowsum
#pragma unroll
    for (int mi = 0; mi < 2; mi++) {
        const int rloc = warp_m * 32 + mi * 16 + (lane >> 2);
        const int rbase = row0 + rloc;
        const float iv0 = inv_s[rloc];
        const float iv1 = inv_s[rloc + 8];
        float* base = out + (size_t)bz * PS * PD;
#pragma unroll
        for (int n = 0; n < 8; n++) {
            const int cb = col0 + warp_n * 64 + n * 8 + 2 * (lane & 3);
            float2 v0 = make_float2(acc[mi][n][0] * iv0, acc[mi][n][1] * iv0);
            float2 v1 = make_float2(acc[mi][n][2] * iv1, acc[mi][n][3] * iv1);
            *reinterpret_cast<float2*>(base + (size_t)rbase * PD + cb) = v0;
            *reinterpret_cast<float2*>(base + (size_t)(rbase + 8) * PD + cb) = v1;
        }
    }
}

// ---------------------------------------------------------------------------
// Merged splits: x, Wq, Wk, Wv -> plain fp16 (one launch)
// ---------------------------------------------------------------------------
struct SplitArgs {
    const float* src[4];
    __half* dst[4];
};

__global__ void __launch_bounds__(256)
split_all(SplitArgs sa)
{
    int bid = blockIdx.x;
    int which, boff;
    if (bid < 16384) { which = 0; boff = bid; }
    else { which = 1 + ((bid - 16384) >> 10); boff = (bid - 16384) & 1023; }

    size_t i = (size_t)boff * 256 + threadIdx.x;
    float4 v = reinterpret_cast<const float4*>(sa.src[which])[i];
    reinterpret_cast<uint2*>(sa.dst[which])[i] =
        make_uint2(pk2h(v.x, v.y), pk2h(v.z, v.w));
}

// ---------------------------------------------------------------------------
// Launcher
// ---------------------------------------------------------------------------
extern "C" void kernel_launch(void* const* d_in, const int* in_sizes, int n_in,
                              void* d_out, int out_size)
{
    (void)in_sizes; (void)n_in; (void)out_size;
    const float* x  = (const float*)d_in[0];
    const float* Wq = (const float*)d_in[1];
    const float* bq = (const float*)d_in[2];
    const float* Wk = (const float*)d_in[3];
    const float* bk = (const float*)d_in[4];
    const float* Wv = (const float*)d_in[5];
    const float* bv = (const float*)d_in[6];
    float* out = (float*)d_out;

    __half *x16, *Wq16, *Wk16, *Wv16, *Q16, *K16, *V16, *Pf;
    float *psum;
    cudaGetSymbolAddress((void**)&x16,  g_x16);
    cudaGetSymbolAddress((void**)&Wq16, g_Wq16);
    cudaGetSymbolAddress((void**)&Wk16, g_Wk16);
    cudaGetSymbolAddress((void**)&Wv16, g_Wv16);
    cudaGetSymbolAddress((void**)&Q16,  g_Q16);
    cudaGetSymbolAddress((void**)&K16,  g_K16);
    cudaGetSymbolAddress((void**)&V16,  g_V16);
    cudaGetSymbolAddress((void**)&Pf,   g_Pf);
    cudaGetSymbolAddress((void**)&psum, g_psum);

    cudaFuncSetAttribute((const void*)gemm_nt<0>,
                         cudaFuncAttributeMaxDynamicSharedMemorySize, NT_SMEM);
    cudaFuncSetAttribute((const void*)gemm_nt<1>,
                         cudaFuncAttributeMaxDynamicSharedMemorySize, NT_SMEM);
    cudaFuncSetAttribute((const void*)gemm_pv,
                         cudaFuncAttributeMaxDynamicSharedMemorySize, PV_SMEM);

    // 1) merged splits: x + Wq/Wk/Wv -> plain fp16
    SplitArgs sa;
    sa.src[0] = x;  sa.dst[0] = x16;
    sa.src[1] = Wq; sa.dst[1] = Wq16;
    sa.src[2] = Wk; sa.dst[2] = Wk16;
    sa.src[3] = Wv; sa.dst[3] = Wv16;
    split_all<<<16384 + 3 * 1024, 256>>>(sa);

    // 2) merged projections: z=0/1/2 -> Q/K/V plain fp16
    ProjArgs pa;
    pa.s[0] = { Wq16, bq, Q16 };
    pa.s[1] = { Wk16, bk, K16 };
    pa.s[2] = { Wv16, bv, V16 };
    ProjArgs dummy = {};
    dim3 gp(PD / 128, MROWS / 128, 3);
    gemm_nt<0><<<gp, 128, NT_SMEM>>>(x16, nullptr, pa, nullptr, nullptr);

    // 3) scores + fused exp -> fp16 P, psum partials
    dim3 gs(PS / 128, PS / 128, PB);
    gemm_nt<1><<<gs, 128, NT_SMEM>>>(Q16, K16, dummy, Pf, psum);

    // 4) out = (P @ V) * inv   (rowsum folded into PV prologue)
    dim3 go(PD / 128, PS / 64, PB);
    gemm_pv<<<go, 128, PV_SMEM>>>(Pf, V16, out, psum);
}